// round 11
// baseline (speedup 1.0000x reference)
#include <cuda_runtime.h>
#include <math.h>
#include <stdint.h>

#define KDIM 512
#define NTHREADS 256
#define WARPS_PER_BLOCK (NTHREADS / 32)
#define NBLOCKS (148 * 2)            // 2 blocks/SM (smem-limited), persistent grid-stride
#define STAGES 3
#define STAGE_BYTES 4096             // one row: 2KB x + 2KB t
#define SMEM_DYN (WARPS_PER_BLOCK * STAGES * STAGE_BYTES)   // 96 KB

// Deterministic per-block partial sums (no device allocation allowed).
__device__ double g_partials[NBLOCKS];
__device__ unsigned int g_count = 0;   // reset by last block each call -> graph-replay safe

__device__ __forceinline__ uint32_t smem_u32(const void* p) {
    return (uint32_t)__cvta_generic_to_shared(p);
}
__device__ __forceinline__ void cp_async16(uint32_t dst, const void* src) {
    asm volatile("cp.async.cg.shared.global [%0], [%1], 16;" :: "r"(dst), "l"(src));
}
__device__ __forceinline__ void cp_commit() {
    asm volatile("cp.async.commit_group;");
}
template <int N>
__device__ __forceinline__ void cp_wait() {
    asm volatile("cp.async.wait_group %0;" :: "n"(N));
}

__global__ __launch_bounds__(NTHREADS) void sce_main_kernel(
    const float* __restrict__ input,
    const float* __restrict__ target,
    const float* __restrict__ weight,
    float* __restrict__ out,
    int n_rows)
{
    extern __shared__ char stage_mem[];   // [warp][stage][4KB]
    __shared__ float s_w[KDIM];
    __shared__ double s_warp[WARPS_PER_BLOCK];
    __shared__ bool s_last;

    const int tid = threadIdx.x;
    for (int i = tid; i < KDIM; i += NTHREADS) s_w[i] = weight[i];
    __syncthreads();

    const int warp = tid >> 5;
    const int lane = tid & 31;
    const int gwarp = blockIdx.x * WARPS_PER_BLOCK + warp;
    const int nwarps = NBLOCKS * WARPS_PER_BLOCK;

    // This warp's private 3-stage ring. Lane l copies/reads bytes [16*(l+32j)]
    // of each half — the same thread writes and reads each 16B chunk, so the
    // per-thread cp.async group semantics make the pipeline warp-local:
    // no __syncthreads, no mbarriers, no register double-buffers.
    const uint32_t ring = smem_u32(stage_mem) + warp * (STAGES * STAGE_BYTES);

    // Issue one row's 8 cp.asyncs into stage s (predicated), always commit.
    auto issue_row = [&](int k, int s) {
        const int r = gwarp + k * nwarps;
        if (r < n_rows) {
            const char* xg = (const char*)(input  + (size_t)r * KDIM);
            const char* tg = (const char*)(target + (size_t)r * KDIM);
            const uint32_t xs = ring + s * STAGE_BYTES;
            const uint32_t ts = xs + 2048;
            #pragma unroll
            for (int j = 0; j < 4; j++) {
                const int off = 16 * (lane + 32 * j);
                cp_async16(xs + off, xg + off);
                cp_async16(ts + off, tg + off);
            }
        }
        cp_commit();   // empty group when out of rows keeps wait_group accounting fixed
    };

    double acc = 0.0;

    issue_row(0, 0);
    issue_row(1, 1);

    for (int k = 0; gwarp + k * nwarps < n_rows; k++) {
        issue_row(k + 2, (k + 2) % STAGES);
        cp_wait<2>();   // oldest pending group (row k) now resident in smem

        const uint32_t xs = ring + (k % STAGES) * STAGE_BYTES;
        const uint32_t ts = xs + 2048;

        float4 x[4], t[4];
        #pragma unroll
        for (int j = 0; j < 4; j++) {
            const int off = 16 * (lane + 32 * j);
            asm volatile("ld.shared.v4.f32 {%0,%1,%2,%3}, [%4];"
                         : "=f"(x[j].x), "=f"(x[j].y), "=f"(x[j].z), "=f"(x[j].w)
                         : "r"(xs + off));
        }
        #pragma unroll
        for (int j = 0; j < 4; j++) {
            const int off = 16 * (lane + 32 * j);
            asm volatile("ld.shared.v4.f32 {%0,%1,%2,%3}, [%4];"
                         : "=f"(t[j].x), "=f"(t[j].y), "=f"(t[j].z), "=f"(t[j].w)
                         : "r"(ts + off));
        }

        // Row max
        float m = -INFINITY;
        #pragma unroll
        for (int j = 0; j < 4; j++)
            m = fmaxf(m, fmaxf(fmaxf(x[j].x, x[j].y), fmaxf(x[j].z, x[j].w)));
        #pragma unroll
        for (int o = 16; o > 0; o >>= 1)
            m = fmaxf(m, __shfl_xor_sync(0xFFFFFFFFu, m, o));

        // Fused: sum exp(x-m), sum t*w, sum t*w*x
        float se = 0.f, tw = 0.f, twx = 0.f;
        #pragma unroll
        for (int j = 0; j < 4; j++) {
            const int c = (lane + 32 * j) * 4;
            const float w0 = s_w[c + 0], w1 = s_w[c + 1];
            const float w2 = s_w[c + 2], w3 = s_w[c + 3];
            se += __expf(x[j].x - m) + __expf(x[j].y - m)
                + __expf(x[j].z - m) + __expf(x[j].w - m);
            const float a0 = t[j].x * w0, a1 = t[j].y * w1;
            const float a2 = t[j].z * w2, a3 = t[j].w * w3;
            tw  += (a0 + a1) + (a2 + a3);
            twx += (a0 * x[j].x + a1 * x[j].y) + (a2 * x[j].z + a3 * x[j].w);
        }
        #pragma unroll
        for (int o = 16; o > 0; o >>= 1) {
            se  += __shfl_xor_sync(0xFFFFFFFFu, se, o);
            tw  += __shfl_xor_sync(0xFFFFFFFFu, tw, o);
            twx += __shfl_xor_sync(0xFFFFFFFFu, twx, o);
        }

        const float lse = m + __logf(se);
        acc += (double)(tw * lse - twx);
    }
    cp_wait<0>();   // drain trailing (possibly empty) groups

    if (lane == 0) s_warp[warp] = acc;
    __syncthreads();
    if (tid == 0) {
        double b = 0.0;
        #pragma unroll
        for (int i = 0; i < WARPS_PER_BLOCK; i++) b += s_warp[i];
        g_partials[blockIdx.x] = b;
        __threadfence();
        unsigned int prev = atomicAdd(&g_count, 1u);
        s_last = (prev == NBLOCKS - 1);
    }
    __syncthreads();

    // Last block performs the deterministic final reduction.
    if (s_last) {
        __shared__ double s_red[NTHREADS];
        double a = 0.0;
        for (int i = tid; i < NBLOCKS; i += NTHREADS)
            a += __ldcg(&g_partials[i]);
        s_red[tid] = a;
        __syncthreads();
        for (int o = NTHREADS / 2; o > 0; o >>= 1) {
            if (tid < o) s_red[tid] += s_red[tid + o];
            __syncthreads();
        }
        if (tid == 0) {
            out[0] = (float)(s_red[0] / (double)n_rows);
            g_count = 0;   // reset for next graph replay
            __threadfence();
        }
    }
}

extern "C" void kernel_launch(void* const* d_in, const int* in_sizes, int n_in,
                              void* d_out, int out_size)
{
    const float* input  = (const float*)d_in[0];
    const float* target = (const float*)d_in[1];
    const float* weight = (const float*)d_in[2];
    float* out = (float*)d_out;

    const int n_rows = in_sizes[0] / KDIM;

    cudaFuncSetAttribute(sce_main_kernel,
                         cudaFuncAttributeMaxDynamicSharedMemorySize, SMEM_DYN);
    sce_main_kernel<<<NBLOCKS, NTHREADS, SMEM_DYN>>>(input, target, weight, out, n_rows);
}

// round 13
// speedup vs baseline: 1.2237x; 1.2237x over previous
#include <cuda_runtime.h>
#include <math.h>

#define KDIM 512
#define NTHREADS 256
#define NBLOCKS 1184
#define WARPS_PER_BLOCK (NTHREADS / 32)

// Deterministic per-block partial sums (no device allocation allowed).
__device__ double g_partials[NBLOCKS];
__device__ unsigned int g_count = 0;   // reset by last block each call -> graph-replay safe

__global__ __launch_bounds__(NTHREADS) void sce_main_kernel(
    const float* __restrict__ input,
    const float* __restrict__ target,
    const float* __restrict__ weight,
    float* __restrict__ out,
    int n_rows)
{
    __shared__ float s_w[KDIM];
    __shared__ double s_warp[WARPS_PER_BLOCK];
    __shared__ bool s_last;

    const int tid = threadIdx.x;
    // Stage weight vector in shared (2 KB).
    for (int i = tid; i < KDIM; i += NTHREADS) s_w[i] = weight[i];
    __syncthreads();

    const int warp = tid >> 5;
    const int lane = tid & 31;
    const int gwarp = blockIdx.x * WARPS_PER_BLOCK + warp;
    const int nwarps = NBLOCKS * WARPS_PER_BLOCK;

    double acc = 0.0;

    for (int row = gwarp; row < n_rows; row += nwarps) {
        const float4* xr = (const float4*)(input + (size_t)row * KDIM);
        const float4* tr = (const float4*)(target + (size_t)row * KDIM);

        float4 x[4], t[4];
        // 8 back-to-back 128B coalesced loads per warp — front-batched for MLP.
        // __ldcs: data is read exactly once -> evict-first in L1/L2 (the ONLY
        // change vs the proven 157.8us R2 kernel; same SASS shape, regs, occ).
        #pragma unroll
        for (int j = 0; j < 4; j++) x[j] = __ldcs(&xr[lane + 32 * j]);
        #pragma unroll
        for (int j = 0; j < 4; j++) t[j] = __ldcs(&tr[lane + 32 * j]);

        // Row max
        float m = -INFINITY;
        #pragma unroll
        for (int j = 0; j < 4; j++) {
            m = fmaxf(m, fmaxf(fmaxf(x[j].x, x[j].y), fmaxf(x[j].z, x[j].w)));
        }
        #pragma unroll
        for (int o = 16; o > 0; o >>= 1)
            m = fmaxf(m, __shfl_xor_sync(0xFFFFFFFFu, m, o));

        // Fused: sum exp(x-m), sum t*w, sum t*w*x (single register pass)
        float se = 0.f, tw = 0.f, twx = 0.f;
        #pragma unroll
        for (int j = 0; j < 4; j++) {
            const int c = (lane + 32 * j) * 4;
            const float w0 = s_w[c + 0], w1 = s_w[c + 1];
            const float w2 = s_w[c + 2], w3 = s_w[c + 3];
            se += __expf(x[j].x - m) + __expf(x[j].y - m)
                + __expf(x[j].z - m) + __expf(x[j].w - m);
            const float a0 = t[j].x * w0, a1 = t[j].y * w1;
            const float a2 = t[j].z * w2, a3 = t[j].w * w3;
            tw  += (a0 + a1) + (a2 + a3);
            twx += (a0 * x[j].x + a1 * x[j].y) + (a2 * x[j].z + a3 * x[j].w);
        }
        #pragma unroll
        for (int o = 16; o > 0; o >>= 1) {
            se  += __shfl_xor_sync(0xFFFFFFFFu, se, o);
            tw  += __shfl_xor_sync(0xFFFFFFFFu, tw, o);
            twx += __shfl_xor_sync(0xFFFFFFFFu, twx, o);
        }

        const float lse = m + __logf(se);
        acc += (double)(tw * lse - twx);   // per_row = sum t*w*(lse - x)
    }

    if (lane == 0) s_warp[warp] = acc;
    __syncthreads();
    if (tid == 0) {
        double b = 0.0;
        #pragma unroll
        for (int i = 0; i < WARPS_PER_BLOCK; i++) b += s_warp[i];
        g_partials[blockIdx.x] = b;
        __threadfence();
        unsigned int prev = atomicAdd(&g_count, 1u);
        s_last = (prev == NBLOCKS - 1);
    }
    __syncthreads();

    // Last block performs the deterministic final reduction.
    if (s_last) {
        __shared__ double s_red[NTHREADS];
        double a = 0.0;
        for (int i = tid; i < NBLOCKS; i += NTHREADS)
            a += __ldcg(&g_partials[i]);
        s_red[tid] = a;
        __syncthreads();
        for (int o = NTHREADS / 2; o > 0; o >>= 1) {
            if (tid < o) s_red[tid] += s_red[tid + o];
            __syncthreads();
        }
        if (tid == 0) {
            out[0] = (float)(s_red[0] / (double)n_rows);
            g_count = 0;   // reset for next graph replay
            __threadfence();
        }
    }
}

extern "C" void kernel_launch(void* const* d_in, const int* in_sizes, int n_in,
                              void* d_out, int out_size)
{
    const float* input  = (const float*)d_in[0];
    const float* target = (const float*)d_in[1];
    const float* weight = (const float*)d_in[2];
    float* out = (float*)d_out;

    const int n_rows = in_sizes[0] / KDIM;

    sce_main_kernel<<<NBLOCKS, NTHREADS>>>(input, target, weight, out, n_rows);
}